// round 14
// baseline (speedup 1.0000x reference)
#include <cuda_runtime.h>
#include <cuda_fp16.h>

// Swin window attention: one 512-thread CTA per QUAD of 8x8 windows, as two fully
// decoupled 8-warp groups (each a window pair). x-in loaded 64B-coalesced per group
// (no cross-group LN exchange); out+residual via 128B-coalesced staged epilogue
// (the ONLY CTA-wide barrier). Fragment tables stay L1-resident (2 CTAs/SM).
// Q never touches smem; max-free half2 softmax (log2-domain); bias as MMA C-init;
// row sums via ones-column MMA.

#define NQUAD  2048
#define TPB    512
#define LOG2E  1.4426950408889634f
#define ONESH2 0x3C003C00u

// smem layout (bytes)
#define OFF_XN   0        // half [256][72] 36864  (Z all 4 windows; later AO)
#define OFF_KV   36864    // 2 groups x 18432: K|V [64][136] per window / staging [128][72]
#define SMEM_BYTES 73728

#define BAR_GRP(id) asm volatile("bar.sync %0, 256;" :: "r"(id) : "memory")

// pre-baked tables (prep kernel fills these)
__device__ unsigned g_qkvfrag[3072 * 2];   // [ntile0..23][kt0..3][lane][2]  (LN+scale folded)
__device__ unsigned g_projfrag[1024 * 2];  // [ntile0..7][kt][lane][2]
__device__ unsigned g_qkvbh[96];           // half2 qkv bias per col-pair (scale folded)
__device__ unsigned g_biasfh[2048 * 4];    // [gwarp][mt][quad][lane] uint4 (lane-contiguous)

__device__ __forceinline__ unsigned packh2f(float lo, float hi) {
    __half2 h = __floats2half2_rn(lo, hi);
    return *reinterpret_cast<unsigned*>(&h);
}

__global__ void prep_kernel(const float* __restrict__ qw, const float* __restrict__ pw,
                            const float* __restrict__ nw, const float* __restrict__ nb,
                            const float* __restrict__ rpb) {
    int idx = blockIdx.x * blockDim.x + threadIdx.x;   // 32 blocks * 256 = 8192

    if (idx < 3072) {  // qkv weight fragments (norm_w + q-scale*log2e folded)
        int lane = idx & 31, kt = (idx >> 5) & 3, ntile = idx >> 7;
        int n  = ntile * 8 + (lane >> 2);
        int k0 = kt * 16 + (lane & 3) * 2;
        float sc = (n < 64) ? 0.25f * LOG2E : 1.0f;
        const float* wr = qw + n * 64;
        g_qkvfrag[idx * 2 + 0] = packh2f(wr[k0] * nw[k0] * sc,         wr[k0 + 1] * nw[k0 + 1] * sc);
        g_qkvfrag[idx * 2 + 1] = packh2f(wr[k0 + 8] * nw[k0 + 8] * sc, wr[k0 + 9] * nw[k0 + 9] * sc);
    }
    if (idx < 1024) {  // proj weight fragments
        int lane = idx & 31, kt = (idx >> 5) & 3, ntile = idx >> 7;
        int n  = ntile * 8 + (lane >> 2);
        int k0 = kt * 16 + (lane & 3) * 2;
        const float* wr = pw + n * 64;
        g_projfrag[idx * 2 + 0] = packh2f(wr[k0],     wr[k0 + 1]);
        g_projfrag[idx * 2 + 1] = packh2f(wr[k0 + 8], wr[k0 + 9]);
    }
    if (idx < 96) {    // folded LN-bias through qkv (per output col pair), scale folded
        float b0 = 0.f, b1 = 0.f;
        int c = idx * 2;
        for (int k = 0; k < 64; k++) {
            b0 += nb[k] * qw[c * 64 + k];
            b1 += nb[k] * qw[(c + 1) * 64 + k];
        }
        float sc = (c < 64) ? 0.25f * LOG2E : 1.0f;
        g_qkvbh[idx] = packh2f(b0 * sc, b1 * sc);
    }
    if (idx < 2048) {  // bias fragments: uint4 per (gwarp, mt, quad, lane); lane-contiguous
        int lane = idx & 31;
        int qd   = (idx >> 5) & 3;      // quad -> j pair (2*qd, 2*qd+1)
        int mt   = (idx >> 7) & 1;
        int warp = idx >> 8;            // gwarp 0..7
        int h  = warp >> 1;
        int m0 = (warp & 1) * 32;
        int g  = lane >> 2, tig = lane & 3;
        int rr = m0 + mt * 16 + g;
        auto bias = [&](int r, int c) {
            int dy = (r >> 3) - (c >> 3);
            int dx = (r & 7) - (c & 7);
            return rpb[((dy + 7) * 15 + (dx + 7)) * 4 + h] * LOG2E;
        };
        int c0 = (2 * qd) * 8 + tig * 2;
        int c1 = (2 * qd + 1) * 8 + tig * 2;
        g_biasfh[idx * 4 + 0] = packh2f(bias(rr, c0),     bias(rr, c0 + 1));
        g_biasfh[idx * 4 + 1] = packh2f(bias(rr + 8, c0), bias(rr + 8, c0 + 1));
        g_biasfh[idx * 4 + 2] = packh2f(bias(rr, c1),     bias(rr, c1 + 1));
        g_biasfh[idx * 4 + 3] = packh2f(bias(rr + 8, c1), bias(rr + 8, c1 + 1));
    }
}

__device__ __forceinline__ unsigned saddr(const void* p) {
    return (unsigned)__cvta_generic_to_shared(p);
}
__device__ __forceinline__ void ldsm_x4(unsigned a, unsigned& r0, unsigned& r1, unsigned& r2, unsigned& r3) {
    asm volatile("ldmatrix.sync.aligned.m8n8.x4.shared.b16 {%0,%1,%2,%3}, [%4];"
                 : "=r"(r0), "=r"(r1), "=r"(r2), "=r"(r3) : "r"(a));
}
__device__ __forceinline__ void ldsm_x4t(unsigned a, unsigned& r0, unsigned& r1, unsigned& r2, unsigned& r3) {
    asm volatile("ldmatrix.sync.aligned.m8n8.x4.trans.shared.b16 {%0,%1,%2,%3}, [%4];"
                 : "=r"(r0), "=r"(r1), "=r"(r2), "=r"(r3) : "r"(a));
}
__device__ __forceinline__ void mmah(uint2& c, unsigned a0, unsigned a1, unsigned a2, unsigned a3,
                                     unsigned b0, unsigned b1) {
    asm volatile("mma.sync.aligned.m16n8k16.row.col.f16.f16.f16.f16 "
                 "{%0,%1}, {%2,%3,%4,%5}, {%6,%7}, {%0,%1};"
                 : "+r"(c.x), "+r"(c.y)
                 : "r"(a0), "r"(a1), "r"(a2), "r"(a3), "r"(b0), "r"(b1));
}
__device__ __forceinline__ unsigned hadd2u(unsigned a, unsigned b) {
    __half2 r = __hadd2(*(__half2*)&a, *(__half2*)&b);
    return *(unsigned*)&r;
}
__device__ __forceinline__ unsigned ex2h2(unsigned a) {
    unsigned r;
    asm("ex2.approx.f16x2 %0, %1;" : "=r"(r) : "r"(a));
    return r;
}
__device__ __forceinline__ unsigned hmul2u(unsigned a, unsigned b) {
    __half2 r = __hmul2(*(__half2*)&a, *(__half2*)&b);
    return *(unsigned*)&r;
}
__device__ __forceinline__ float2 h2f2(unsigned u) {
    return __half22float2(*(__half2*)&u);
}
__device__ __forceinline__ float hlo2f(unsigned u) {
    return __half2float(__low2half(*(__half2*)&u));
}

__global__ __launch_bounds__(512, 2)
void ewa_kernel(const float* __restrict__ x,
                const float* __restrict__ ascale,
                float* __restrict__ out) {
    extern __shared__ char smem[];
    __half* XN = (__half*)(smem + OFF_XN);        // [256][72]  Z / AO (4 windows)

    const int tid  = threadIdx.x;
    const int lane = tid & 31;
    const int warp = tid >> 5;          // 0..15
    const int grp  = warp >> 3;         // window-pair group (0: win 0-1, 1: win 2-3)
    const int gw   = warp & 7;          // warp within group
    const int gq   = lane >> 2;
    const int tig  = lane & 3;
    const int l2   = lane & 15;
    const int gbar = 1 + grp;           // named barrier id for this group

    __half* KV = (__half*)(smem + OFF_KV) + grp * 9216;   // per-group K|V / staging

    const int pid = blockIdx.x;
    const int b   = pid >> 8;
    const int rem = pid & 255;
    const int wy  = rem >> 3;           // 0..31
    const int wqx = rem & 7;            // quad column: px base = wqx*32

    const int h  = gw >> 1;             // head (phases 2-3)
    const int m0 = (gw & 1) * 32;

    // ---- Phase 1 (group-local): 64B-coalesced load of own pair + warp-local LN ----
    {
        int r    = gw;                  // pixel row (0..7)
        int px16 = lane >> 1;           // 0..15 within the pair
        int hq   = lane & 1;            // channel half
        int tp   = grp * 128 + (px16 >> 3) * 64 + r * 8 + (px16 & 7);
        const float* base = x + (b * 64 + hq * 32) * 65536
                              + (wy * 8 + r) * 256 + wqx * 32 + grp * 16 + px16;
        float v[32];
        #pragma unroll
        for (int i = 0; i < 32; i++) v[i] = base[i * 65536];
        float s = 0.f, ss = 0.f;
        #pragma unroll
        for (int i = 0; i < 32; i++) { s += v[i]; ss += v[i] * v[i]; }
        s  += __shfl_xor_sync(0xffffffffu, s, 1);
        ss += __shfl_xor_sync(0xffffffffu, ss, 1);
        float mu   = s * (1.f / 64.f);
        float var  = ss * (1.f / 64.f) - mu * mu;
        float rstd = rsqrtf(var + 1e-5f);
        unsigned hh[16];
        #pragma unroll
        for (int i = 0; i < 16; i++)
            hh[i] = packh2f((v[2 * i] - mu) * rstd, (v[2 * i + 1] - mu) * rstd);
        uint4* dst = (uint4*)(XN + tp * 72 + hq * 32);
        dst[0] = make_uint4(hh[0],  hh[1],  hh[2],  hh[3]);
        dst[1] = make_uint4(hh[4],  hh[5],  hh[6],  hh[7]);
        dst[2] = make_uint4(hh[8],  hh[9],  hh[10], hh[11]);
        dst[3] = make_uint4(hh[12], hh[13], hh[14], hh[15]);
    }
    BAR_GRP(gbar);   // group-local: own XN rows written by own warps only

    // ---- Phases 2+3 per window within group (KV buffer reused; group-local syncs) ----
    #pragma unroll
    for (int w = 0; w < 2; w++) {
        const int rb = grp * 128 + w * 64;   // row base in XN
        unsigned qa[2][4];

        // Phase 2: QKV GEMM; Q stays in registers, K/V -> smem
        {
            uint2 qacc[2][2], kvacc[2][4];
            #pragma unroll
            for (int mt = 0; mt < 2; mt++) {
                qacc[mt][0] = make_uint2(0u, 0u); qacc[mt][1] = make_uint2(0u, 0u);
                #pragma unroll
                for (int j = 0; j < 4; j++) kvacc[mt][j] = make_uint2(0u, 0u);
            }
            #pragma unroll
            for (int kt = 0; kt < 4; kt++) {
                unsigned a[2][4];
                #pragma unroll
                for (int mt = 0; mt < 2; mt++)
                    ldsm_x4(saddr(XN + (rb + m0 + mt * 16 + l2) * 72 + kt * 16 + (lane >> 4) * 8),
                            a[mt][0], a[mt][1], a[mt][2], a[mt][3]);
                uint2 qb[2], kvb[4];
                #pragma unroll
                for (int j = 0; j < 2; j++)
                    qb[j] = *(const uint2*)(g_qkvfrag + (((h * 2 + j) * 4 + kt) * 32 + lane) * 2);
                #pragma unroll
                for (int j = 0; j < 4; j++)
                    kvb[j] = *(const uint2*)(g_qkvfrag + (((8 + h * 4 + j) * 4 + kt) * 32 + lane) * 2);
                #pragma unroll
                for (int mt = 0; mt < 2; mt++) {
                    #pragma unroll
                    for (int j = 0; j < 2; j++)
                        mmah(qacc[mt][j], a[mt][0], a[mt][1], a[mt][2], a[mt][3], qb[j].x, qb[j].y);
                    #pragma unroll
                    for (int j = 0; j < 4; j++)
                        mmah(kvacc[mt][j], a[mt][0], a[mt][1], a[mt][2], a[mt][3], kvb[j].x, kvb[j].y);
                }
            }
            unsigned bq0 = g_qkvbh[h * 8 + tig];
            unsigned bq1 = g_qkvbh[h * 8 + 4 + tig];
            #pragma unroll
            for (int mt = 0; mt < 2; mt++) {
                qa[mt][0] = hadd2u(qacc[mt][0].x, bq0);
                qa[mt][1] = hadd2u(qacc[mt][0].y, bq0);
                qa[mt][2] = hadd2u(qacc[mt][1].x, bq1);
                qa[mt][3] = hadd2u(qacc[mt][1].y, bq1);
            }
            #pragma unroll
            for (int j = 0; j < 4; j++) {
                int col = h * 32 + j * 8 + tig * 2;
                unsigned bh = g_qkvbh[32 + h * 16 + j * 4 + tig];
                #pragma unroll
                for (int mt = 0; mt < 2; mt++) {
                    int row = m0 + mt * 16 + gq;
                    *(unsigned*)(KV + row * 136 + col)       = hadd2u(kvacc[mt][j].x, bh);
                    *(unsigned*)(KV + (row + 8) * 136 + col) = hadd2u(kvacc[mt][j].y, bh);
                }
            }
        }
        BAR_GRP(gbar);

        // Phase 3: attention
        {
            unsigned kb[8][2];
            #pragma unroll
            for (int jp = 0; jp < 4; jp++) {
                unsigned r0, r1, r2, r3;
                int j  = (lane >> 4);
                int kh = (lane >> 3) & 1;
                ldsm_x4(saddr(KV + ((jp * 2 + j) * 8 + (lane & 7)) * 136 + h * 16 + kh * 8),
                        r0, r1, r2, r3);
                kb[jp * 2 + 0][0] = r0; kb[jp * 2 + 0][1] = r1;
                kb[jp * 2 + 1][0] = r2; kb[jp * 2 + 1][1] = r3;
            }

            #pragma unroll
            for (int mt = 0; mt < 2; mt++) {
                const uint4* bfp = (const uint4*)(g_biasfh) + (gw * 2 + mt) * 128 + lane;
                uint2 s[8];
                #pragma unroll
                for (int qd = 0; qd < 4; qd++) {
                    uint4 bv = bfp[qd * 32];
                    s[2 * qd].x = bv.x;     s[2 * qd].y = bv.y;
                    s[2 * qd + 1].x = bv.z; s[2 * qd + 1].y = bv.w;
                }
                #pragma unroll
                for (int j = 0; j < 8; j++)
                    mmah(s[j], qa[mt][0], qa[mt][1], qa[mt][2], qa[mt][3], kb[j][0], kb[j][1]);

                #pragma unroll
                for (int j = 0; j < 8; j++) {
                    s[j].x = ex2h2(s[j].x);
                    s[j].y = ex2h2(s[j].y);
                }

                uint2 o[2], o2;
                o[0].x = o[0].y = o[1].x = o[1].y = 0u;
                o2.x = o2.y = 0u;
                #pragma unroll
                for (int kt = 0; kt < 4; kt++) {
                    unsigned v0, v1, v2, v3;
                    ldsm_x4t(saddr(KV + (kt * 16 + (lane & 7) + ((lane >> 3) & 1) * 8) * 136
                                   + 64 + h * 16 + (lane >> 4) * 8),
                             v0, v1, v2, v3);
                    mmah(o[0], s[2 * kt].x, s[2 * kt].y, s[2 * kt + 1].x, s[2 * kt + 1].y, v0, v1);
                    mmah(o[1], s[2 * kt].x, s[2 * kt].y, s[2 * kt + 1].x, s[2 * kt + 1].y, v2, v3);
                    mmah(o2,   s[2 * kt].x, s[2 * kt].y, s[2 * kt + 1].x, s[2 * kt + 1].y,
                         ONESH2, ONESH2);
                }

                float f0 = __fdividef(1.f, hlo2f(o2.x));
                float f1 = __fdividef(1.f, hlo2f(o2.y));
                unsigned i0 = packh2f(f0, f0);
                unsigned i1 = packh2f(f1, f1);
                #pragma unroll
                for (int nt = 0; nt < 2; nt++) {
                    int row = rb + m0 + mt * 16 + gq;
                    int col = h * 16 + nt * 8 + tig * 2;
                    *(unsigned*)(XN + row * 72 + col)       = hmul2u(o[nt].x, i0);
                    *(unsigned*)(XN + (row + 8) * 72 + col) = hmul2u(o[nt].y, i1);
                }
            }
        }
        BAR_GRP(gbar);
    }

    // ---- Phase 4: proj GEMM both group windows, stage fp16 results into KV ----
    {
        const int ntb = (gw >> 1) * 2;
        uint2 bf[4][2];
        #pragma unroll
        for (int kt = 0; kt < 4; kt++)
            #pragma unroll
            for (int nt = 0; nt < 2; nt++)
                bf[kt][nt] = *(const uint2*)(g_projfrag + (((ntb + nt) * 4 + kt) * 32 + lane) * 2);

        #pragma unroll
        for (int w = 0; w < 2; w++) {
            const int rb = grp * 128 + w * 64;
            uint2 acc[2][2];
            acc[0][0] = make_uint2(0u, 0u); acc[0][1] = make_uint2(0u, 0u);
            acc[1][0] = make_uint2(0u, 0u); acc[1][1] = make_uint2(0u, 0u);
            #pragma unroll
            for (int kt = 0; kt < 4; kt++) {
                unsigned a[2][4];
                #pragma unroll
                for (int mt = 0; mt < 2; mt++)
                    ldsm_x4(saddr(XN + (rb + m0 + mt * 16 + l2) * 72 + kt * 16 + (lane >> 4) * 8),
                            a[mt][0], a[mt][1], a[mt][2], a[mt][3]);
                #pragma unroll
                for (int mt = 0; mt < 2; mt++)
                    #pragma unroll
                    for (int nt = 0; nt < 2; nt++)
                        mmah(acc[mt][nt], a[mt][0], a[mt][1], a[mt][2], a[mt][3],
                             bf[kt][nt].x, bf[kt][nt].y);
            }
            // stage fp16 proj results: KV reused as [128][72]
            #pragma unroll
            for (int mt = 0; mt < 2; mt++)
                #pragma unroll
                for (int nt = 0; nt < 2; nt++) {
                    int row = w * 64 + m0 + mt * 16 + gq;
                    int col = (ntb + nt) * 8 + tig * 2;
                    *(unsigned*)(KV + row * 72 + col)       = acc[mt][nt].x;
                    *(unsigned*)(KV + (row + 8) * 72 + col) = acc[mt][nt].y;
                }
        }
    }
    __syncthreads();   // the ONLY CTA-wide barrier: epilogue reads both groups' staging

    // ---- Epilogue: 128B-coalesced residual read-modify-write ----
    {
        int r  = warp & 7;
        int hq = warp >> 3;
        int w  = lane >> 3;                 // window 0..3
        const __half* SRC = (const __half*)(smem + OFF_KV) + (w >> 1) * 9216;
        int row = (w & 1) * 64 + r * 8 + (lane & 7);
        const uint4* src = (const uint4*)(SRC + row * 72 + hq * 32);
        uint4 u0 = src[0], u1 = src[1], u2 = src[2], u3 = src[3];
        unsigned hv[16] = {u0.x, u0.y, u0.z, u0.w, u1.x, u1.y, u1.z, u1.w,
                           u2.x, u2.y, u2.z, u2.w, u3.x, u3.y, u3.z, u3.w};
        float ssc = ascale[0];
        int gi = (b * 64 + hq * 32) * 65536 + (wy * 8 + r) * 256 + wqx * 32 + lane;
        #pragma unroll
        for (int i = 0; i < 16; i++) {
            float2 pv = h2f2(hv[i]);
            out[gi]         = x[gi]         + ssc * pv.x;   // channel hq*32 + 2i
            out[gi + 65536] = x[gi + 65536] + ssc * pv.y;   // channel hq*32 + 2i + 1
            gi += 2 * 65536;
        }
    }
}

extern "C" void kernel_launch(void* const* d_in, const int* in_sizes, int n_in,
                              void* d_out, int out_size) {
    const float* x  = (const float*)d_in[0];
    const float* nw = (const float*)d_in[1];
    const float* nb = (const float*)d_in[2];
    const float* qw = (const float*)d_in[3];
    const float* pw = (const float*)d_in[4];
    const float* sc = (const float*)d_in[5];
    const float* rp = (const float*)d_in[6];
    float* out = (float*)d_out;

    cudaFuncSetAttribute(ewa_kernel, cudaFuncAttributeMaxDynamicSharedMemorySize, SMEM_BYTES);

    prep_kernel<<<32, 256>>>(qw, pw, nw, nb, rp);
    ewa_kernel<<<NQUAD, TPB, SMEM_BYTES>>>(x, sc, out);
}

// round 15
// speedup vs baseline: 1.0317x; 1.0317x over previous
#include <cuda_runtime.h>
#include <cuda_fp16.h>

// Swin window attention: one CTA per PAIR of horizontally-adjacent 8x8 windows.
// Each warp-pair (head) produces AND consumes its own head's K/V -> mid-loop
// barriers are 64-thread pair barriers (4 CTA syncs + 1 pair sync total).
// 64B-coalesced global in/out; fragment tables stay L1-resident (4 CTAs/SM).
// Q never touches smem; max-free half2 softmax (log2-domain); bias as MMA C-init;
// row sums via ones-column MMA.

#define NPAIR  4096
#define TPB    256
#define LOG2E  1.4426950408889634f
#define ONESH2 0x3C003C00u

// smem layout (bytes)
#define OFF_XN   0        // half [128][72] 18432  (Z both windows; later AO)
#define OFF_KV   18432    // half [64][136] K|V per window (17408) / staging [128][72]
#define SMEM_BYTES 36864

#define BAR_PAIR(id) asm volatile("bar.sync %0, 64;" :: "r"(id) : "memory")

// pre-baked tables (prep kernel fills these)
__device__ unsigned g_qkvfrag[3072 * 2];   // [ntile0..23][kt0..3][lane][2]  (LN+scale folded)
__device__ unsigned g_projfrag[1024 * 2];  // [ntile0..7][kt][lane][2]
__device__ unsigned g_qkvbh[96];           // half2 qkv bias per col-pair (scale folded)
__device__ unsigned g_biasfh[2048 * 4];    // [warp][mt][quad][lane] uint4 (lane-contiguous)

__device__ __forceinline__ unsigned packh2f(float lo, float hi) {
    __half2 h = __floats2half2_rn(lo, hi);
    return *reinterpret_cast<unsigned*>(&h);
}

__global__ void prep_kernel(const float* __restrict__ qw, const float* __restrict__ pw,
                            const float* __restrict__ nw, const float* __restrict__ nb,
                            const float* __restrict__ rpb) {
    int idx = blockIdx.x * blockDim.x + threadIdx.x;   // 32 blocks * 256 = 8192

    if (idx < 3072) {  // qkv weight fragments (norm_w + q-scale*log2e folded)
        int lane = idx & 31, kt = (idx >> 5) & 3, ntile = idx >> 7;
        int n  = ntile * 8 + (lane >> 2);
        int k0 = kt * 16 + (lane & 3) * 2;
        float sc = (n < 64) ? 0.25f * LOG2E : 1.0f;
        const float* wr = qw + n * 64;
        g_qkvfrag[idx * 2 + 0] = packh2f(wr[k0] * nw[k0] * sc,         wr[k0 + 1] * nw[k0 + 1] * sc);
        g_qkvfrag[idx * 2 + 1] = packh2f(wr[k0 + 8] * nw[k0 + 8] * sc, wr[k0 + 9] * nw[k0 + 9] * sc);
    }
    if (idx < 1024) {  // proj weight fragments
        int lane = idx & 31, kt = (idx >> 5) & 3, ntile = idx >> 7;
        int n  = ntile * 8 + (lane >> 2);
        int k0 = kt * 16 + (lane & 3) * 2;
        const float* wr = pw + n * 64;
        g_projfrag[idx * 2 + 0] = packh2f(wr[k0],     wr[k0 + 1]);
        g_projfrag[idx * 2 + 1] = packh2f(wr[k0 + 8], wr[k0 + 9]);
    }
    if (idx < 96) {    // folded LN-bias through qkv (per output col pair), scale folded
        float b0 = 0.f, b1 = 0.f;
        int c = idx * 2;
        for (int k = 0; k < 64; k++) {
            b0 += nb[k] * qw[c * 64 + k];
            b1 += nb[k] * qw[(c + 1) * 64 + k];
        }
        float sc = (c < 64) ? 0.25f * LOG2E : 1.0f;
        g_qkvbh[idx] = packh2f(b0 * sc, b1 * sc);
    }
    if (idx < 2048) {  // bias fragments: uint4 per (warp, mt, quad, lane); lane-contiguous
        int lane = idx & 31;
        int qd   = (idx >> 5) & 3;      // quad -> j pair (2*qd, 2*qd+1)
        int mt   = (idx >> 7) & 1;
        int warp = idx >> 8;
        int h  = warp >> 1;
        int m0 = (warp & 1) * 32;
        int g  = lane >> 2, tig = lane & 3;
        int rr = m0 + mt * 16 + g;
        auto bias = [&](int r, int c) {
            int dy = (r >> 3) - (c >> 3);
            int dx = (r & 7) - (c & 7);
            return rpb[((dy + 7) * 15 + (dx + 7)) * 4 + h] * LOG2E;
        };
        int c0 = (2 * qd) * 8 + tig * 2;
        int c1 = (2 * qd + 1) * 8 + tig * 2;
        g_biasfh[idx * 4 + 0] = packh2f(bias(rr, c0),     bias(rr, c0 + 1));
        g_biasfh[idx * 4 + 1] = packh2f(bias(rr + 8, c0), bias(rr + 8, c0 + 1));
        g_biasfh[idx * 4 + 2] = packh2f(bias(rr, c1),     bias(rr, c1 + 1));
        g_biasfh[idx * 4 + 3] = packh2f(bias(rr + 8, c1), bias(rr + 8, c1 + 1));
    }
}

__device__ __forceinline__ unsigned saddr(const void* p) {
    return (unsigned)__cvta_generic_to_shared(p);
}
__device__ __forceinline__ void ldsm_x4(unsigned a, unsigned& r0, unsigned& r1, unsigned& r2, unsigned& r3) {
    asm volatile("ldmatrix.sync.aligned.m8n8.x4.shared.b16 {%0,%1,%2,%3}, [%4];"
                 : "=r"(r0), "=r"(r1), "=r"(r2), "=r"(r3) : "r"(a));
}
__device__ __forceinline__ void ldsm_x4t(unsigned a, unsigned& r0, unsigned& r1, unsigned& r2, unsigned& r3) {
    asm volatile("ldmatrix.sync.aligned.m8n8.x4.trans.shared.b16 {%0,%1,%2,%3}, [%4];"
                 : "=r"(r0), "=r"(r1), "=r"(r2), "=r"(r3) : "r"(a));
}
__device__ __forceinline__ void mmah(uint2& c, unsigned a0, unsigned a1, unsigned a2, unsigned a3,
                                     unsigned b0, unsigned b1) {
    asm volatile("mma.sync.aligned.m16n8k16.row.col.f16.f16.f16.f16 "
                 "{%0,%1}, {%2,%3,%4,%5}, {%6,%7}, {%0,%1};"
                 : "+r"(c.x), "+r"(c.y)
                 : "r"(a0), "r"(a1), "r"(a2), "r"(a3), "r"(b0), "r"(b1));
}
__device__ __forceinline__ unsigned hadd2u(unsigned a, unsigned b) {
    __half2 r = __hadd2(*(__half2*)&a, *(__half2*)&b);
    return *(unsigned*)&r;
}
__device__ __forceinline__ unsigned ex2h2(unsigned a) {
    unsigned r;
    asm("ex2.approx.f16x2 %0, %1;" : "=r"(r) : "r"(a));
    return r;
}
__device__ __forceinline__ unsigned hmul2u(unsigned a, unsigned b) {
    __half2 r = __hmul2(*(__half2*)&a, *(__half2*)&b);
    return *(unsigned*)&r;
}
__device__ __forceinline__ float2 h2f2(unsigned u) {
    return __half22float2(*(__half2*)&u);
}
__device__ __forceinline__ float hlo2f(unsigned u) {
    return __half2float(__low2half(*(__half2*)&u));
}

__global__ __launch_bounds__(256, 4)
void ewa_kernel(const float* __restrict__ x,
                const float* __restrict__ ascale,
                float* __restrict__ out) {
    extern __shared__ char smem[];
    __half* XN = (__half*)(smem + OFF_XN);   // [128][72]  Z / AO (both windows)
    __half* KV = (__half*)(smem + OFF_KV);   // [64][136] K|V (per window)

    const int tid  = threadIdx.x;
    const int lane = tid & 31;
    const int warp = tid >> 5;
    const int g    = lane >> 2;
    const int tig  = lane & 3;
    const int l2   = lane & 15;

    const int pid = blockIdx.x;
    const int b   = pid >> 9;
    const int rem = pid & 511;
    const int wy  = rem >> 4;      // 0..31
    const int wpx = rem & 15;      // window-pair column: px base = wpx*16

    const int h  = warp >> 1;      // head (phases 2-3): this pair owns head h's K/V
    const int m0 = (warp & 1) * 32;

    // ---- Phase 1: 64B-coalesced load of both windows + in-register LayerNorm ----
    {
        int r    = warp;           // pixel row within window (0..7)
        int px16 = lane >> 1;      // 0..15 across the pair
        int hq   = lane & 1;       // channel half (0: c 0-31, 1: c 32-63)
        int w    = px16 >> 3;
        int tp   = w * 64 + r * 8 + (px16 & 7);    // token index in pair coords
        const float* base = x + (b * 64 + hq * 32) * 65536
                              + (wy * 8 + r) * 256 + wpx * 16 + px16;
        float v[32];
        #pragma unroll
        for (int i = 0; i < 32; i++) v[i] = base[i * 65536];
        float s = 0.f, ss = 0.f;
        #pragma unroll
        for (int i = 0; i < 32; i++) { s += v[i]; ss += v[i] * v[i]; }
        s  += __shfl_xor_sync(0xffffffffu, s, 1);
        ss += __shfl_xor_sync(0xffffffffu, ss, 1);
        float mu   = s * (1.f / 64.f);
        float var  = ss * (1.f / 64.f) - mu * mu;
        float rstd = rsqrtf(var + 1e-5f);
        unsigned hh[16];
        #pragma unroll
        for (int i = 0; i < 16; i++)
            hh[i] = packh2f((v[2 * i] - mu) * rstd, (v[2 * i + 1] - mu) * rstd);
        uint4* dst = (uint4*)(XN + tp * 72 + hq * 32);
        dst[0] = make_uint4(hh[0],  hh[1],  hh[2],  hh[3]);
        dst[1] = make_uint4(hh[4],  hh[5],  hh[6],  hh[7]);
        dst[2] = make_uint4(hh[8],  hh[9],  hh[10], hh[11]);
        dst[3] = make_uint4(hh[12], hh[13], hh[14], hh[15]);
    }
    __syncthreads();

    // ---- Phases 2+3 per window (KV buffer reused; own-head K/V -> pair-local WAR) ----
    #pragma unroll
    for (int w = 0; w < 2; w++) {
        const int rb = w * 64;     // row base in XN for this window
        unsigned qa[2][4];

        // Phase 2: QKV GEMM; Q stays in registers, own head's K/V -> smem
        {
            uint2 qacc[2][2], kvacc[2][4];
            #pragma unroll
            for (int mt = 0; mt < 2; mt++) {
                qacc[mt][0] = make_uint2(0u, 0u); qacc[mt][1] = make_uint2(0u, 0u);
                #pragma unroll
                for (int j = 0; j < 4; j++) kvacc[mt][j] = make_uint2(0u, 0u);
            }
            #pragma unroll
            for (int kt = 0; kt < 4; kt++) {
                unsigned a[2][4];
                #pragma unroll
                for (int mt = 0; mt < 2; mt++)
                    ldsm_x4(saddr(XN + (rb + m0 + mt * 16 + l2) * 72 + kt * 16 + (lane >> 4) * 8),
                            a[mt][0], a[mt][1], a[mt][2], a[mt][3]);
                uint2 qb[2], kvb[4];
                #pragma unroll
                for (int j = 0; j < 2; j++)
                    qb[j] = *(const uint2*)(g_qkvfrag + (((h * 2 + j) * 4 + kt) * 32 + lane) * 2);
                // own head's K (ntiles 8+2h, 9+2h) and V (ntiles 16+2h, 17+2h)
                #pragma unroll
                for (int j = 0; j < 4; j++) {
                    int ntile = (j < 2) ? (8 + 2 * h + j) : (16 + 2 * h + (j - 2));
                    kvb[j] = *(const uint2*)(g_qkvfrag + ((ntile * 4 + kt) * 32 + lane) * 2);
                }
                #pragma unroll
                for (int mt = 0; mt < 2; mt++) {
                    #pragma unroll
                    for (int j = 0; j < 2; j++)
                        mmah(qacc[mt][j], a[mt][0], a[mt][1], a[mt][2], a[mt][3], qb[j].x, qb[j].y);
                    #pragma unroll
                    for (int j = 0; j < 4; j++)
                        mmah(kvacc[mt][j], a[mt][0], a[mt][1], a[mt][2], a[mt][3], kvb[j].x, kvb[j].y);
                }
            }
            // Q: D-frag (+bias) == A-frag for QK^T
            unsigned bq0 = g_qkvbh[h * 8 + tig];
            unsigned bq1 = g_qkvbh[h * 8 + 4 + tig];
            #pragma unroll
            for (int mt = 0; mt < 2; mt++) {
                qa[mt][0] = hadd2u(qacc[mt][0].x, bq0);
                qa[mt][1] = hadd2u(qacc[mt][0].y, bq0);
                qa[mt][2] = hadd2u(qacc[mt][1].x, bq1);
                qa[mt][3] = hadd2u(qacc[mt][1].y, bq1);
            }
            // own head's K -> smem cols h*16..; V -> 64 + h*16..
            #pragma unroll
            for (int j = 0; j < 4; j++) {
                int ntile = (j < 2) ? (8 + 2 * h + j) : (16 + 2 * h + (j - 2));
                int col   = ((j < 2) ? (h * 16 + j * 8) : (64 + h * 16 + (j - 2) * 8)) + tig * 2;
                unsigned bh = g_qkvbh[ntile * 4 + tig];
                #pragma unroll
                for (int mt = 0; mt < 2; mt++) {
                    int row = m0 + mt * 16 + g;
                    *(unsigned*)(KV + row * 136 + col)       = hadd2u(kvacc[mt][j].x, bh);
                    *(unsigned*)(KV + (row + 8) * 136 + col) = hadd2u(kvacc[mt][j].y, bh);
                }
            }
        }
        // Z(w) fully consumed + own K/V visible to the pair: CTA sync (P3 writes AO
        // into XN rows rb.. which other pairs read as Z during their P2 of this w)
        __syncthreads();

        // Phase 3: attention (own head's K/V; pair-local data)
        {
            unsigned kb[8][2];
            #pragma unroll
            for (int jp = 0; jp < 4; jp++) {        // K fragments via ldmatrix.x4
                unsigned r0, r1, r2, r3;
                int j  = (lane >> 4);               // n-tile within pair
                int kh = (lane >> 3) & 1;
                ldsm_x4(saddr(KV + ((jp * 2 + j) * 8 + (lane & 7)) * 136 + h * 16 + kh * 8),
                        r0, r1, r2, r3);
                kb[jp * 2 + 0][0] = r0; kb[jp * 2 + 0][1] = r1;
                kb[jp * 2 + 1][0] = r2; kb[jp * 2 + 1][1] = r3;
            }

            #pragma unroll
            for (int mt = 0; mt < 2; mt++) {
                // bias fragments: 4 lane-contiguous LDG.128
                const uint4* bfp = (const uint4*)(g_biasfh) + (warp * 2 + mt) * 128 + lane;
                uint2 s[8];
                #pragma unroll
                for (int qd = 0; qd < 4; qd++) {
                    uint4 bv = bfp[qd * 32];
                    s[2 * qd].x = bv.x;     s[2 * qd].y = bv.y;
                    s[2 * qd + 1].x = bv.z; s[2 * qd + 1].y = bv.w;
                }
                #pragma unroll
                for (int j = 0; j < 8; j++)
                    mmah(s[j], qa[mt][0], qa[mt][1], qa[mt][2], qa[mt][3], kb[j][0], kb[j][1]);

                // max-free: p = 2^l directly (logits bounded, fp16-safe)
                #pragma unroll
                for (int j = 0; j < 8; j++) {
                    s[j].x = ex2h2(s[j].x);
                    s[j].y = ex2h2(s[j].y);
                }

                // AV + row-sum (P @ ones) via MMA
                uint2 o[2], o2;
                o[0].x = o[0].y = o[1].x = o[1].y = 0u;
                o2.x = o2.y = 0u;
                #pragma unroll
                for (int kt = 0; kt < 4; kt++) {
                    unsigned v0, v1, v2, v3;
                    ldsm_x4t(saddr(KV + (kt * 16 + (lane & 7) + ((lane >> 3) & 1) * 8) * 136
                                   + 64 + h * 16 + (lane >> 4) * 8),
                             v0, v1, v2, v3);
                    mmah(o[0], s[2 * kt].x, s[2 * kt].y, s[2 * kt + 1].x, s[2 * kt + 1].y, v0, v1);
                    mmah(o[1], s[2 * kt].x, s[2 * kt].y, s[2 * kt + 1].x, s[2 * kt + 1].y, v2, v3);
                    mmah(o2,   s[2 * kt].x, s[2 * kt].y, s[2 * kt + 1].x, s[2 * kt + 1].y,
                         ONESH2, ONESH2);
                }

                float f0 = __fdividef(1.f, hlo2f(o2.x));
                float f1 = __fdividef(1.f, hlo2f(o2.y));
                unsigned i0 = packh2f(f0, f0);
                unsigned i1 = packh2f(f1, f1);
                #pragma unroll
                for (int nt = 0; nt < 2; nt++) {
                    int row = rb + m0 + mt * 16 + g;
                    int col = h * 16 + nt * 8 + tig * 2;
                    *(unsigned*)(XN + row * 72 + col)       = hmul2u(o[nt].x, i0);
                    *(unsigned*)(XN + (row + 8) * 72 + col) = hmul2u(o[nt].y, i1);
                }
            }
        }
        // KV WAR before this pair's P2(w1) rewrite: pair-local barrier (w0 only);
        // after w1, a CTA sync before P4 (reads all pairs' AO)
        if (w == 0) BAR_PAIR(1 + h);
    }
    __syncthreads();

    // ---- Phase 4: proj GEMM [128,64]x[64,64] + residual + write out (fp16 acc) ----
    {
        const int ntb = (warp >> 1) * 2;      // ntile base (8-col tiles)
        uint2 bf[4][2];
        #pragma unroll
        for (int kt = 0; kt < 4; kt++)
            #pragma unroll
            for (int nt = 0; nt < 2; nt++)
                bf[kt][nt] = *(const uint2*)(g_projfrag + (((ntb + nt) * 4 + kt) * 32 + lane) * 2);

        #pragma unroll
        for (int w = 0; w < 2; w++) {
            const int rb = w * 64;
            uint2 acc[2][2];
            acc[0][0] = make_uint2(0u, 0u); acc[0][1] = make_uint2(0u, 0u);
            acc[1][0] = make_uint2(0u, 0u); acc[1][1] = make_uint2(0u, 0u);
            #pragma unroll
            for (int kt = 0; kt < 4; kt++) {
                unsigned a[2][4];
                #pragma unroll
                for (int mt = 0; mt < 2; mt++)
                    ldsm_x4(saddr(XN + (rb + m0 + mt * 16 + l2) * 72 + kt * 16 + (lane >> 4) * 8),
                            a[mt][0], a[mt][1], a[mt][2], a[mt][3]);
                #pragma unroll
                for (int mt = 0; mt < 2; mt++)
                    #pragma unroll
                    for (int nt = 0; nt < 2; nt++)
                        mmah(acc[mt][nt], a[mt][0], a[mt][1], a[mt][2], a[mt][3],
                             bf[kt][nt].x, bf[kt][nt].y);
            }
            float ssc = ascale[0];
            #pragma unroll
            for (int mt = 0; mt < 2; mt++)
                #pragma unroll
                for (int nt = 0; nt < 2; nt++) {
                    int ch = (ntb + nt) * 8 + tig * 2;
                    float2 lo = h2f2(acc[mt][nt].x);   // rows rb+m0+mt*16+g
                    float2 hi = h2f2(acc[mt][nt].y);   // rows +8
                    #pragma unroll
                    for (int hf = 0; hf < 2; hf++) {
                        int row = m0 + mt * 16 + g + hf * 8;   // token within window
                        float2 v = hf ? hi : lo;
                        int gi0 = ((b * 64 + ch) * 256 + wy * 8 + (row >> 3)) * 256
                                  + wpx * 16 + w * 8 + (row & 7);
                        int gi1 = gi0 + 65536;   // ch+1
                        out[gi0] = x[gi0] + ssc * v.x;
                        out[gi1] = x[gi1] + ssc * v.y;
                    }
                }
        }
    }
}

extern "C" void kernel_launch(void* const* d_in, const int* in_sizes, int n_in,
                              void* d_out, int out_size) {
    const float* x  = (const float*)d_in[0];
    const float* nw = (const float*)d_in[1];
    const float* nb = (const float*)d_in[2];
    const float* qw = (const float*)d_in[3];
    const float* pw = (const float*)d_in[4];
    const float* sc = (const float*)d_in[5];
    const float* rp = (const float*)d_in[6];
    float* out = (float*)d_out;

    cudaFuncSetAttribute(ewa_kernel, cudaFuncAttributeMaxDynamicSharedMemorySize, SMEM_BYTES);

    prep_kernel<<<32, 256>>>(qw, pw, nw, nb, rp);
    ewa_kernel<<<NPAIR, TPB, SMEM_BYTES>>>(x, sc, out);
}

// round 16
// speedup vs baseline: 1.1016x; 1.0678x over previous
#include <cuda_runtime.h>
#include <cuda_fp16.h>

// Swin window attention: one CTA per PAIR of horizontally-adjacent 8x8 windows.
// R11 structure (empirically optimal barriers/CTA shape) + single-pass V fragments:
// both mt logit tiles computed first, then V loaded ONCE per kt feeding all AV MMAs.
// 64B-coalesced global in/out; fragment tables L1-resident (4 CTAs/SM).
// Q never touches smem; max-free half2 softmax (log2-domain); bias as MMA C-init;
// row sums via ones-column MMA.

#define NPAIR  4096
#define TPB    256
#define LOG2E  1.4426950408889634f
#define ONESH2 0x3C003C00u

// smem layout (bytes)
#define OFF_XN   0        // half [128][72] 18432  (Z both windows; later AO)
#define OFF_KV   18432    // half [64][136] K|V per window (17408) / staging [128][72]
#define SMEM_BYTES 36864

// pre-baked tables (prep kernel fills these)
__device__ unsigned g_qkvfrag[3072 * 2];   // [ntile0..23][kt0..3][lane][2]  (LN+scale folded)
__device__ unsigned g_projfrag[1024 * 2];  // [ntile0..7][kt][lane][2]
__device__ unsigned g_qkvbh[96];           // half2 qkv bias per col-pair (scale folded)
__device__ unsigned g_biasfh[2048 * 4];    // [warp][mt][quad][lane] uint4 (lane-contiguous)

__device__ __forceinline__ unsigned packh2f(float lo, float hi) {
    __half2 h = __floats2half2_rn(lo, hi);
    return *reinterpret_cast<unsigned*>(&h);
}

__global__ void prep_kernel(const float* __restrict__ qw, const float* __restrict__ pw,
                            const float* __restrict__ nw, const float* __restrict__ nb,
                            const float* __restrict__ rpb) {
    int idx = blockIdx.x * blockDim.x + threadIdx.x;   // 32 blocks * 256 = 8192

    if (idx < 3072) {  // qkv weight fragments (norm_w + q-scale*log2e folded)
        int lane = idx & 31, kt = (idx >> 5) & 3, ntile = idx >> 7;
        int n  = ntile * 8 + (lane >> 2);
        int k0 = kt * 16 + (lane & 3) * 2;
        float sc = (n < 64) ? 0.25f * LOG2E : 1.0f;
        const float* wr = qw + n * 64;
        g_qkvfrag[idx * 2 + 0] = packh2f(wr[k0] * nw[k0] * sc,         wr[k0 + 1] * nw[k0 + 1] * sc);
        g_qkvfrag[idx * 2 + 1] = packh2f(wr[k0 + 8] * nw[k0 + 8] * sc, wr[k0 + 9] * nw[k0 + 9] * sc);
    }
    if (idx < 1024) {  // proj weight fragments
        int lane = idx & 31, kt = (idx >> 5) & 3, ntile = idx >> 7;
        int n  = ntile * 8 + (lane >> 2);
        int k0 = kt * 16 + (lane & 3) * 2;
        const float* wr = pw + n * 64;
        g_projfrag[idx * 2 + 0] = packh2f(wr[k0],     wr[k0 + 1]);
        g_projfrag[idx * 2 + 1] = packh2f(wr[k0 + 8], wr[k0 + 9]);
    }
    if (idx < 96) {    // folded LN-bias through qkv (per output col pair), scale folded
        float b0 = 0.f, b1 = 0.f;
        int c = idx * 2;
        for (int k = 0; k < 64; k++) {
            b0 += nb[k] * qw[c * 64 + k];
            b1 += nb[k] * qw[(c + 1) * 64 + k];
        }
        float sc = (c < 64) ? 0.25f * LOG2E : 1.0f;
        g_qkvbh[idx] = packh2f(b0 * sc, b1 * sc);
    }
    if (idx < 2048) {  // bias fragments: uint4 per (warp, mt, quad, lane); lane-contiguous
        int lane = idx & 31;
        int qd   = (idx >> 5) & 3;      // quad -> j pair (2*qd, 2*qd+1)
        int mt   = (idx >> 7) & 1;
        int warp = idx >> 8;
        int h  = warp >> 1;
        int m0 = (warp & 1) * 32;
        int g  = lane >> 2, tig = lane & 3;
        int rr = m0 + mt * 16 + g;
        auto bias = [&](int r, int c) {
            int dy = (r >> 3) - (c >> 3);
            int dx = (r & 7) - (c & 7);
            return rpb[((dy + 7) * 15 + (dx + 7)) * 4 + h] * LOG2E;
        };
        int c0 = (2 * qd) * 8 + tig * 2;
        int c1 = (2 * qd + 1) * 8 + tig * 2;
        g_biasfh[idx * 4 + 0] = packh2f(bias(rr, c0),     bias(rr, c0 + 1));
        g_biasfh[idx * 4 + 1] = packh2f(bias(rr + 8, c0), bias(rr + 8, c0 + 1));
        g_biasfh[idx * 4 + 2] = packh2f(bias(rr, c1),     bias(rr, c1 + 1));
        g_biasfh[idx * 4 + 3] = packh2f(bias(rr + 8, c1), bias(rr + 8, c1 + 1));
    }
}

__device__ __forceinline__ unsigned saddr(const void* p) {
    return (unsigned)__cvta_generic_to_shared(p);
}
__device__ __forceinline__ void ldsm_x4(unsigned a, unsigned& r0, unsigned& r1, unsigned& r2, unsigned& r3) {
    asm volatile("ldmatrix.sync.aligned.m8n8.x4.shared.b16 {%0,%1,%2,%3}, [%4];"
                 : "=r"(r0), "=r"(r1), "=r"(r2), "=r"(r3) : "r"(a));
}
__device__ __forceinline__ void ldsm_x4t(unsigned a, unsigned& r0, unsigned& r1, unsigned& r2, unsigned& r3) {
    asm volatile("ldmatrix.sync.aligned.m8n8.x4.trans.shared.b16 {%0,%1,%2,%3}, [%4];"
                 : "=r"(r0), "=r"(r1), "=r"(r2), "=r"(r3) : "r"(a));
}
__device__ __forceinline__ void mmah(uint2& c, unsigned a0, unsigned a1, unsigned a2, unsigned a3,
                                     unsigned b0, unsigned b1) {
    asm volatile("mma.sync.aligned.m16n8k16.row.col.f16.f16.f16.f16 "
                 "{%0,%1}, {%2,%3,%4,%5}, {%6,%7}, {%0,%1};"
                 : "+r"(c.x), "+r"(c.y)
                 : "r"(a0), "r"(a1), "r"(a2), "r"(a3), "r"(b0), "r"(b1));
}
__device__ __forceinline__ unsigned hadd2u(unsigned a, unsigned b) {
    __half2 r = __hadd2(*(__half2*)&a, *(__half2*)&b);
    return *(unsigned*)&r;
}
__device__ __forceinline__ unsigned ex2h2(unsigned a) {
    unsigned r;
    asm("ex2.approx.f16x2 %0, %1;" : "=r"(r) : "r"(a));
    return r;
}
__device__ __forceinline__ unsigned hmul2u(unsigned a, unsigned b) {
    __half2 r = __hmul2(*(__half2*)&a, *(__half2*)&b);
    return *(unsigned*)&r;
}
__device__ __forceinline__ float2 h2f2(unsigned u) {
    return __half22float2(*(__half2*)&u);
}
__device__ __forceinline__ float hlo2f(unsigned u) {
    return __half2float(__low2half(*(__half2*)&u));
}

__global__ __launch_bounds__(256, 4)
void ewa_kernel(const float* __restrict__ x,
                const float* __restrict__ ascale,
                float* __restrict__ out) {
    extern __shared__ char smem[];
    __half* XN = (__half*)(smem + OFF_XN);   // [128][72]  Z / AO (both windows)
    __half* KV = (__half*)(smem + OFF_KV);   // [64][136] K|V (per window) / staging

    const int tid  = threadIdx.x;
    const int lane = tid & 31;
    const int warp = tid >> 5;
    const int g    = lane >> 2;
    const int tig  = lane & 3;
    const int l2   = lane & 15;

    const int pid = blockIdx.x;
    const int b   = pid >> 9;
    const int rem = pid & 511;
    const int wy  = rem >> 4;      // 0..31
    const int wpx = rem & 15;      // window-pair column: px base = wpx*16

    const int h  = warp >> 1;      // head (phases 2-3)
    const int m0 = (warp & 1) * 32;

    // ---- Phase 1: 64B-coalesced load of both windows + in-register LayerNorm ----
    {
        int r    = warp;           // pixel row within window (0..7)
        int px16 = lane >> 1;      // 0..15 across the pair
        int hq   = lane & 1;       // channel half (0: c 0-31, 1: c 32-63)
        int w    = px16 >> 3;
        int tp   = w * 64 + r * 8 + (px16 & 7);    // token index in pair coords
        const float* base = x + (b * 64 + hq * 32) * 65536
                              + (wy * 8 + r) * 256 + wpx * 16 + px16;
        float v[32];
        #pragma unroll
        for (int i = 0; i < 32; i++) v[i] = base[i * 65536];
        float s = 0.f, ss = 0.f;
        #pragma unroll
        for (int i = 0; i < 32; i++) { s += v[i]; ss += v[i] * v[i]; }
        s  += __shfl_xor_sync(0xffffffffu, s, 1);
        ss += __shfl_xor_sync(0xffffffffu, ss, 1);
        float mu   = s * (1.f / 64.f);
        float var  = ss * (1.f / 64.f) - mu * mu;
        float rstd = rsqrtf(var + 1e-5f);
        unsigned hh[16];
        #pragma unroll
        for (int i = 0; i < 16; i++)
            hh[i] = packh2f((v[2 * i] - mu) * rstd, (v[2 * i + 1] - mu) * rstd);
        uint4* dst = (uint4*)(XN + tp * 72 + hq * 32);
        dst[0] = make_uint4(hh[0],  hh[1],  hh[2],  hh[3]);
        dst[1] = make_uint4(hh[4],  hh[5],  hh[6],  hh[7]);
        dst[2] = make_uint4(hh[8],  hh[9],  hh[10], hh[11]);
        dst[3] = make_uint4(hh[12], hh[13], hh[14], hh[15]);
    }
    __syncthreads();

    // ---- Phases 2+3 per window (KV buffer reused) ----
    #pragma unroll
    for (int w = 0; w < 2; w++) {
        const int rb = w * 64;     // row base in XN for this window
        unsigned qa[2][4];

        // Phase 2: QKV GEMM; Q stays in registers, K/V -> smem
        {
            uint2 qacc[2][2], kvacc[2][4];
            #pragma unroll
            for (int mt = 0; mt < 2; mt++) {
                qacc[mt][0] = make_uint2(0u, 0u); qacc[mt][1] = make_uint2(0u, 0u);
                #pragma unroll
                for (int j = 0; j < 4; j++) kvacc[mt][j] = make_uint2(0u, 0u);
            }
            #pragma unroll
            for (int kt = 0; kt < 4; kt++) {
                unsigned a[2][4];
                #pragma unroll
                for (int mt = 0; mt < 2; mt++)
                    ldsm_x4(saddr(XN + (rb + m0 + mt * 16 + l2) * 72 + kt * 16 + (lane >> 4) * 8),
                            a[mt][0], a[mt][1], a[mt][2], a[mt][3]);
                uint2 qb[2], kvb[4];
                #pragma unroll
                for (int j = 0; j < 2; j++)
                    qb[j] = *(const uint2*)(g_qkvfrag + (((h * 2 + j) * 4 + kt) * 32 + lane) * 2);
                #pragma unroll
                for (int j = 0; j < 4; j++)
                    kvb[j] = *(const uint2*)(g_qkvfrag + (((8 + h * 4 + j) * 4 + kt) * 32 + lane) * 2);
                #pragma unroll
                for (int mt = 0; mt < 2; mt++) {
                    #pragma unroll
                    for (int j = 0; j < 2; j++)
                        mmah(qacc[mt][j], a[mt][0], a[mt][1], a[mt][2], a[mt][3], qb[j].x, qb[j].y);
                    #pragma unroll
                    for (int j = 0; j < 4; j++)
                        mmah(kvacc[mt][j], a[mt][0], a[mt][1], a[mt][2], a[mt][3], kvb[j].x, kvb[j].y);
                }
            }
            unsigned bq0 = g_qkvbh[h * 8 + tig];
            unsigned bq1 = g_qkvbh[h * 8 + 4 + tig];
            #pragma unroll
            for (int mt = 0; mt < 2; mt++) {
                qa[mt][0] = hadd2u(qacc[mt][0].x, bq0);
                qa[mt][1] = hadd2u(qacc[mt][0].y, bq0);
                qa[mt][2] = hadd2u(qacc[mt][1].x, bq1);
                qa[mt][3] = hadd2u(qacc[mt][1].y, bq1);
            }
            // K/V -> smem (smem col = global col - 64)
            #pragma unroll
            for (int j = 0; j < 4; j++) {
                int col = h * 32 + j * 8 + tig * 2;
                unsigned bh = g_qkvbh[32 + h * 16 + j * 4 + tig];
                #pragma unroll
                for (int mt = 0; mt < 2; mt++) {
                    int row = m0 + mt * 16 + g;
                    *(unsigned*)(KV + row * 136 + col)       = hadd2u(kvacc[mt][j].x, bh);
                    *(unsigned*)(KV + (row + 8) * 136 + col) = hadd2u(kvacc[mt][j].y, bh);
                }
            }
        }
        __syncthreads();

        // Phase 3: attention. QK^T for BOTH mt tiles first, then V loaded once per kt.
        {
            // bias fragments for both mts: 8 lane-contiguous LDG.128 batched
            const uint4* bfp = (const uint4*)(g_biasfh) + (warp * 2) * 128 + lane;
            uint2 s0[8], s1[8];
            #pragma unroll
            for (int qd = 0; qd < 4; qd++) {
                uint4 b0 = bfp[qd * 32];
                uint4 b1 = bfp[128 + qd * 32];
                s0[2 * qd].x = b0.x;     s0[2 * qd].y = b0.y;
                s0[2 * qd + 1].x = b0.z; s0[2 * qd + 1].y = b0.w;
                s1[2 * qd].x = b1.x;     s1[2 * qd].y = b1.y;
                s1[2 * qd + 1].x = b1.z; s1[2 * qd + 1].y = b1.w;
            }

            // K fragments
            unsigned kb[8][2];
            #pragma unroll
            for (int jp = 0; jp < 4; jp++) {
                unsigned r0, r1, r2, r3;
                int j  = (lane >> 4);
                int kh = (lane >> 3) & 1;
                ldsm_x4(saddr(KV + ((jp * 2 + j) * 8 + (lane & 7)) * 136 + h * 16 + kh * 8),
                        r0, r1, r2, r3);
                kb[jp * 2 + 0][0] = r0; kb[jp * 2 + 0][1] = r1;
                kb[jp * 2 + 1][0] = r2; kb[jp * 2 + 1][1] = r3;
            }

            #pragma unroll
            for (int j = 0; j < 8; j++) {
                mmah(s0[j], qa[0][0], qa[0][1], qa[0][2], qa[0][3], kb[j][0], kb[j][1]);
                mmah(s1[j], qa[1][0], qa[1][1], qa[1][2], qa[1][3], kb[j][0], kb[j][1]);
            }
            // qa, kb dead past this point

            // max-free: p = 2^l (logits bounded, fp16-safe)
            #pragma unroll
            for (int j = 0; j < 8; j++) {
                s0[j].x = ex2h2(s0[j].x);  s0[j].y = ex2h2(s0[j].y);
                s1[j].x = ex2h2(s1[j].x);  s1[j].y = ex2h2(s1[j].y);
            }

            // AV + row sums: V fragments loaded ONCE per kt, feeding both mts
            uint2 o0[2], o1[2], z0, z1;
            o0[0] = make_uint2(0u, 0u); o0[1] = make_uint2(0u, 0u);
            o1[0] = make_uint2(0u, 0u); o1[1] = make_uint2(0u, 0u);
            z0 = make_uint2(0u, 0u);    z1 = make_uint2(0u, 0u);
            #pragma unroll
            for (int kt = 0; kt < 4; kt++) {
                unsigned v0, v1, v2, v3;
                ldsm_x4t(saddr(KV + (kt * 16 + (lane & 7) + ((lane >> 3) & 1) * 8) * 136
                               + 64 + h * 16 + (lane >> 4) * 8),
                         v0, v1, v2, v3);
                mmah(o0[0], s0[2 * kt].x, s0[2 * kt].y, s0[2 * kt + 1].x, s0[2 * kt + 1].y, v0, v1);
                mmah(o0[1], s0[2 * kt].x, s0[2 * kt].y, s0[2 * kt + 1].x, s0[2 * kt + 1].y, v2, v3);
                mmah(o1[0], s1[2 * kt].x, s1[2 * kt].y, s1[2 * kt + 1].x, s1[2 * kt + 1].y, v0, v1);
                mmah(o1[1], s1[2 * kt].x, s1[2 * kt].y, s1[2 * kt + 1].x, s1[2 * kt + 1].y, v2, v3);
                mmah(z0, s0[2 * kt].x, s0[2 * kt].y, s0[2 * kt + 1].x, s0[2 * kt + 1].y,
                     ONESH2, ONESH2);
                mmah(z1, s1[2 * kt].x, s1[2 * kt].y, s1[2 * kt + 1].x, s1[2 * kt + 1].y,
                     ONESH2, ONESH2);
            }

            float f00 = __fdividef(1.f, hlo2f(z0.x));
            float f01 = __fdividef(1.f, hlo2f(z0.y));
            float f10 = __fdividef(1.f, hlo2f(z1.x));
            float f11 = __fdividef(1.f, hlo2f(z1.y));
            unsigned i00 = packh2f(f00, f00), i01 = packh2f(f01, f01);
            unsigned i10 = packh2f(f10, f10), i11 = packh2f(f11, f11);
            #pragma unroll
            for (int nt = 0; nt < 2; nt++) {
                int col = h * 16 + nt * 8 + tig * 2;
                int r0 = rb + m0 + g;
                int r1 = rb + m0 + 16 + g;
                *(unsigned*)(XN + r0 * 72 + col)        = hmul2u(o0[nt].x, i00);
                *(unsigned*)(XN + (r0 + 8) * 72 + col)  = hmul2u(o0[nt].y, i01);
                *(unsigned*)(XN + r1 * 72 + col)        = hmul2u(o1[nt].x, i10);
                *(unsigned*)(XN + (r1 + 8) * 72 + col)  = hmul2u(o1[nt].y, i11);
            }
        }
        __syncthreads();
    }

    // ---- Phase 4: proj GEMM both windows, stage fp16 results into KV buffer ----
    {
        const int ntb = (warp >> 1) * 2;
        uint2 bf[4][2];
        #pragma unroll
        for (int kt = 0; kt < 4; kt++)
            #pragma unroll
            for (int nt = 0; nt < 2; nt++)
                bf[kt][nt] = *(const uint2*)(g_projfrag + (((ntb + nt) * 4 + kt) * 32 + lane) * 2);

        #pragma unroll
        for (int w = 0; w < 2; w++) {
            const int rb = w * 64;
            uint2 acc[2][2];
            acc[0][0] = make_uint2(0u, 0u); acc[0][1] = make_uint2(0u, 0u);
            acc[1][0] = make_uint2(0u, 0u); acc[1][1] = make_uint2(0u, 0u);
            #pragma unroll
            for (int kt = 0; kt < 4; kt++) {
                unsigned a[2][4];
                #pragma unroll
                for (int mt = 0; mt < 2; mt++)
                    ldsm_x4(saddr(XN + (rb + m0 + mt * 16 + l2) * 72 + kt * 16 + (lane >> 4) * 8),
                            a[mt][0], a[mt][1], a[mt][2], a[mt][3]);
                #pragma unroll
                for (int mt = 0; mt < 2; mt++)
                    #pragma unroll
                    for (int nt = 0; nt < 2; nt++)
                        mmah(acc[mt][nt], a[mt][0], a[mt][1], a[mt][2], a[mt][3],
                             bf[kt][nt].x, bf[kt][nt].y);
            }
            // stage fp16 proj results: KV reused as [128][72]
            #pragma unroll
            for (int mt = 0; mt < 2; mt++)
                #pragma unroll
                for (int nt = 0; nt < 2; nt++) {
                    int row = w * 64 + m0 + mt * 16 + g;
                    int col = (ntb + nt) * 8 + tig * 2;
                    *(unsigned*)(KV + row * 72 + col)       = acc[mt][nt].x;
                    *(unsigned*)(KV + (row + 8) * 72 + col) = acc[mt][nt].y;
                }
        }
    }
    __syncthreads();

    // ---- Epilogue: 64B-coalesced residual read-modify-write ----
    {
        int r    = warp;
        int px16 = lane >> 1;
        int hq   = lane & 1;
        int w    = px16 >> 3;
        int tp   = w * 64 + r * 8 + (px16 & 7);
        const uint4* src = (const uint4*)(KV + tp * 72 + hq * 32);
        uint4 u0 = src[0], u1 = src[1], u2 = src[2], u3 = src[3];
        unsigned hv[16] = {u0.x, u0.y, u0.z, u0.w, u1.x, u1.y, u1.z, u1.w,
                           u2.x, u2.y, u2.z, u2.w, u3.x, u3.y, u3.z, u3.w};
        float ssc = ascale[0];
        int gi = (b * 64 + hq * 32) * 65536 + (wy * 8 + r) * 256 + wpx * 16 + px16;
        #pragma unroll
        for (int i = 0; i < 16; i++) {
            float2 pv = h2f2(hv[i]);
            out[gi]         = x[gi]         + ssc * pv.x;   // channel hq*32 + 2i
            out[gi + 65536] = x[gi + 65536] + ssc * pv.y;   // channel hq*32 + 2i + 1
            gi += 2 * 65536;
        }
    }
}

extern "C" void kernel_launch(void* const* d_in, const int* in_sizes, int n_in,
                              void* d_out, int out_size) {
    const float* x  = (const float*)d_in[0];
    const float* nw = (const float*)d_in[1];
    const float* nb = (const float*)d_in[2];
    const float* qw = (const float*)d_in[3];
    const float* pw = (const float*)d_in[4];
    const float* sc = (const float*)d_in[5];
    const float* rp = (const float*)d_in[6];
    float* out = (float*)d_out;

    cudaFuncSetAttribute(ewa_kernel, cudaFuncAttributeMaxDynamicSharedMemorySize, SMEM_BYTES);

    prep_kernel<<<32, 256>>>(qw, pw, nw, nb, rp);
    ewa_kernel<<<NPAIR, TPB, SMEM_BYTES>>>(x, sc, out);
}